// round 14
// baseline (speedup 1.0000x reference)
#include <cuda_runtime.h>
#include <cuda_fp16.h>
#include <math.h>
#include <stdint.h>

#define DIMM   1024
#define DEPTH  4
#define HEADS  16
#define DHEAD  64
#define MLPD   4096
#define INNER  1024
#define BATCH  4
#define SEQ    1024
#define TOK    (BATCH*SEQ)
#define QKV3   (3*INNER)

// ---------------- scratch ----------------------------------------------------
__device__ __half g_h  [TOK*DIMM];                 // LN output (fp16)
__device__ __half g_qkv[TOK*QKV3];
__device__ __half g_att[TOK*INNER];
__device__ __half g_mlp[TOK*MLPD];
// fp16 weights, ORIGINAL [K][N] layout (no transpose)
__device__ __half g_wqkv[(size_t)DEPTH*DIMM*QKV3];
__device__ __half g_wout[(size_t)DEPTH*INNER*DIMM];
__device__ __half g_w1  [(size_t)DEPTH*DIMM*MLPD];
__device__ __half g_w2  [(size_t)DEPTH*MLPD*DIMM];

__device__ __forceinline__ uint32_t smem_u32(const void* p){
    return (uint32_t)__cvta_generic_to_shared(p);
}
__device__ __forceinline__ uint32_t ph(float a, float b){
    __half2 h = __floats2half2_rn(a, b);
    return *reinterpret_cast<uint32_t*>(&h);
}
#define CP16(dst, src) asm volatile("cp.async.cg.shared.global [%0], [%1], 16;\n" :: "r"(dst), "l"(src))
#define CP_COMMIT()    asm volatile("cp.async.commit_group;\n" ::: "memory")
#define CP_WAIT1()     asm volatile("cp.async.wait_group 1;\n" ::: "memory")
#define CP_WAIT0()     asm volatile("cp.async.wait_group 0;\n" ::: "memory")

#define MMA_F16(d, a, b) \
  asm volatile("mma.sync.aligned.m16n8k16.row.col.f32.f16.f16.f32 " \
    "{%0,%1,%2,%3},{%4,%5,%6,%7},{%8,%9},{%0,%1,%2,%3};" \
    : "+f"((d)[0]),"+f"((d)[1]),"+f"((d)[2]),"+f"((d)[3]) \
    : "r"((a)[0]),"r"((a)[1]),"r"((a)[2]),"r"((a)[3]),"r"((b)[0]),"r"((b)[1]))

__device__ __forceinline__ void ldsm_x4(uint32_t* r, uint32_t a){
    asm volatile("ldmatrix.sync.aligned.m8n8.x4.shared.b16 {%0,%1,%2,%3}, [%4];"
        : "=r"(r[0]),"=r"(r[1]),"=r"(r[2]),"=r"(r[3]) : "r"(a));
}
__device__ __forceinline__ void ldsm_x4t(uint32_t* r, uint32_t a){
    asm volatile("ldmatrix.sync.aligned.m8n8.x4.trans.shared.b16 {%0,%1,%2,%3}, [%4];"
        : "=r"(r[0]),"=r"(r[1]),"=r"(r[2]),"=r"(r[3]) : "r"(a));
}

// ---------------- streaming f32 -> fp16 convert, 4 float4/thread -------------
__global__ void cvt16(const float* __restrict__ in, __half* __restrict__ out, int n16)
{
    const int base = blockIdx.x * 1024 + threadIdx.x;   // in float4 units
    const float4* p4 = (const float4*)in;
    uint2* o2 = (uint2*)out;
    if (blockIdx.x * 1024 + 1024 <= n16 * 4){
        float4 a = __ldcs(&p4[base]),     b = __ldcs(&p4[base+256]);
        float4 c = __ldcs(&p4[base+512]), d = __ldcs(&p4[base+768]);
        uint2 oa = {ph(a.x,a.y), ph(a.z,a.w)};
        uint2 ob = {ph(b.x,b.y), ph(b.z,b.w)};
        uint2 oc = {ph(c.x,c.y), ph(c.z,c.w)};
        uint2 od = {ph(d.x,d.y), ph(d.z,d.w)};
        o2[base] = oa; o2[base+256] = ob; o2[base+512] = oc; o2[base+768] = od;
    } else {
        #pragma unroll
        for (int j = 0; j < 4; j++){
            const int i = base + j*256;
            if (i < n16 * 4){
                float4 a = __ldcs(&p4[i]);
                uint2 o = {ph(a.x,a.y), ph(a.z,a.w)};
                o2[i] = o;
            }
        }
    }
}

// ---------------- LayerNorm: warp-per-row (8 rows/block), shfl-only ----------
__global__ void ln_kernel(const float* __restrict__ in, __half* __restrict__ out,
                          const float* __restrict__ gg, const float* __restrict__ bb)
{
    const int warp = threadIdx.x >> 5, lane = threadIdx.x & 31;
    const int row = blockIdx.x * 8 + warp;
    const float4* p = (const float4*)(in + (size_t)row * DIMM);

    float4 v[8];
    float s = 0.f, s2 = 0.f;
    #pragma unroll
    for (int j = 0; j < 8; j++){
        v[j] = p[lane + j*32];
        s  += v[j].x + v[j].y + v[j].z + v[j].w;
        s2 += v[j].x*v[j].x + v[j].y*v[j].y + v[j].z*v[j].z + v[j].w*v[j].w;
    }
    #pragma unroll
    for (int o = 16; o > 0; o >>= 1){
        s  += __shfl_xor_sync(0xffffffffu, s,  o);
        s2 += __shfl_xor_sync(0xffffffffu, s2, o);
    }
    const float mean = s * (1.0f/DIMM);
    const float var  = s2 * (1.0f/DIMM) - mean*mean;
    const float rs   = rsqrtf(var + 1e-5f);

    uint2* orow = (uint2*)(out + (size_t)row * DIMM);
    #pragma unroll
    for (int j = 0; j < 8; j++){
        const float4 gv = ((const float4*)gg)[lane + j*32];
        const float4 bv = ((const float4*)bb)[lane + j*32];
        uint2 o;
        o.x = ph((v[j].x - mean)*rs*gv.x + bv.x, (v[j].y - mean)*rs*gv.y + bv.y);
        o.y = ph((v[j].z - mean)*rs*gv.z + bv.z, (v[j].w - mean)*rs*gv.w + bv.w);
        orow[lane + j*32] = o;
    }
}

// ---------------- FP16 GEMM: 128x128, B [K][N] via trans-ldsm, BK=64 ---------
// R10 schedule (measured optimum): prefetch after compute, 3 stages, 2 CTA/SM.
// EPI: 1 +bias+GELU -> fp16 ; 2 +bias+residual -> f32 ; 3 plain -> fp16
#define ABYH  18432            // 128*144
#define BBYH  17408            // 64*272
#define STGH  (ABYH+BBYH)      // 35840
#define NSTG  3
#define SMTOT (NSTG*STGH)      // 107520

template<int EPI>
__global__ void __launch_bounds__(256, 2)
hgemm(const __half* __restrict__ A, const __half* __restrict__ B,
      void* __restrict__ Cv, const float* __restrict__ bias,
      const float* __restrict__ R, int M, int Nn, int K)
{
    extern __shared__ char smc[];
    const uint32_t sb = smem_u32(smc);
    const int tid = threadIdx.x, warp = tid >> 5, lane = tid & 31;
    const int g = lane >> 2, t = lane & 3;
    const int wm = (warp >> 2) * 64;
    const int wn = (warp & 3) * 32;
    const int brow = blockIdx.y * 128;
    const int bcol = blockIdx.x * 128;

    float acc[4][4][4];
    #pragma unroll
    for (int i = 0; i < 4; i++)
      #pragma unroll
      for (int j = 0; j < 4; j++)
        { acc[i][j][0]=0.f; acc[i][j][1]=0.f; acc[i][j][2]=0.f; acc[i][j][3]=0.f; }

    auto prefetch = [&](int blk){
        const uint32_t ab = sb + (uint32_t)((blk % NSTG) * STGH);
        const uint32_t bb = ab + ABYH;
        const int kof = blk * 64;
        #pragma unroll
        for (int j = 0; j < 4; j++){
            const int c = tid + j*256;
            const int ar = c >> 3, aq = c & 7;
            CP16(ab + (uint32_t)(ar*144 + aq*16), A + (size_t)(brow+ar)*K + kof + aq*8);
            const int br2 = c >> 4, bq = c & 15;
            CP16(bb + (uint32_t)(br2*272 + bq*16), B + (size_t)(kof+br2)*Nn + bcol + bq*8);
        }
    };

    prefetch(0); CP_COMMIT();
    prefetch(1); CP_COMMIT();

    const uint32_t aoff = (uint32_t)((wm + (lane & 15))*144 + (lane >> 4)*16);
    const uint32_t boffl = (uint32_t)((lane & 15)*272 + (wn + ((lane >> 4) & 1)*8)*2) + ABYH;

    const int nk = K >> 6;
    for (int i = 0; i < nk; i++){
        CP_WAIT1();
        __syncthreads();
        const uint32_t stg = sb + (uint32_t)((i % NSTG) * STGH);
        #pragma unroll
        for (int s = 0; s < 4; s++){
            uint32_t af[4][4], bq2[2][4];
            #pragma unroll
            for (int mt = 0; mt < 4; mt++)
                ldsm_x4(af[mt], stg + aoff + (uint32_t)(mt*2304 + s*32));
            #pragma unroll
            for (int np = 0; np < 2; np++)
                ldsm_x4t(bq2[np], stg + boffl + (uint32_t)(s*4352 + np*32));
            #pragma unroll
            for (int mt = 0; mt < 4; mt++)
              #pragma unroll
              for (int nt = 0; nt < 4; nt++)
                MMA_F16(acc[mt][nt], af[mt], &bq2[nt >> 1][(nt & 1)*2]);
        }
        if (i + 2 < nk) prefetch(i + 2);
        CP_COMMIT();
    }

    #pragma unroll
    for (int mt = 0; mt < 4; mt++){
        const int r0 = brow + wm + mt*16 + g;
        #pragma unroll
        for (int nt = 0; nt < 4; nt++){
            const int c = bcol + wn + nt*8 + 2*t;
            float v[4] = {acc[mt][nt][0], acc[mt][nt][1], acc[mt][nt][2], acc[mt][nt][3]};
            if (EPI == 1 || EPI == 2){
                const float b0 = bias[c], b1 = bias[c+1];
                v[0]+=b0; v[1]+=b1; v[2]+=b0; v[3]+=b1;
            }
            if (EPI == 1){
                #pragma unroll
                for (int q = 0; q < 4; q++)
                    v[q] = 0.5f * v[q] * (1.0f + erff(v[q] * 0.70710678118654752f));
            }
            if (EPI == 2){
                float* Cf = (float*)Cv;
                const float2 r0v = *(const float2*)(R + (size_t)r0*Nn + c);
                const float2 r1v = *(const float2*)(R + (size_t)(r0+8)*Nn + c);
                float2 o0 = {v[0]+r0v.x, v[1]+r0v.y}, o1 = {v[2]+r1v.x, v[3]+r1v.y};
                *(float2*)(Cf + (size_t)r0    *Nn + c) = o0;
                *(float2*)(Cf + (size_t)(r0+8)*Nn + c) = o1;
            } else {
                __half* Ch = (__half*)Cv;
                *(uint32_t*)(Ch + (size_t)r0    *Nn + c) = ph(v[0], v[1]);
                *(uint32_t*)(Ch + (size_t)(r0+8)*Nn + c) = ph(v[2], v[3]);
            }
        }
    }
}

// ---------------- Fused fp16 flash attention, half2 exp2 softmax -------------
#define FKV   18432
#define FLSM  (3*FKV + 4096)

__global__ void __launch_bounds__(256, 2)
flash_kernel(const __half* __restrict__ qkv, __half* __restrict__ att,
             const int* __restrict__ mnp, const int* __restrict__ mbt)
{
    extern __shared__ char fsm[];
    const uint32_t base = smem_u32(fsm);
    float* cmask = (float*)(fsm + 3*FKV);
    const float L2E = 1.4426950408889634f;

    const int tid = threadIdx.x, warp = tid >> 5, lane = tid & 31;
    const int g = lane >> 2, t = lane & 3;
    const int bh = blockIdx.y, b = bh >> 4, h = bh & 15;
    const int i0 = blockIdx.x * 128;

    const __half* qb    = qkv + (size_t)(b*SEQ + i0) * QKV3 + h*DHEAD;
    const __half* kbase = qkv + (size_t)(b*SEQ) * QKV3 + INNER   + h*DHEAD;
    const __half* vbase = qkv + (size_t)(b*SEQ) * QKV3 + 2*INNER + h*DHEAD;

    {
        const int j = tid * 4;
        const int4 a = *(const int4*)(mnp + b*SEQ + j);
        const int4 c = *(const int4*)(mbt + b*SEQ + j);
        cmask[j+0] = (a.x != 0 && c.x != 1) ? 1.f : 0.f;
        cmask[j+1] = (a.y != 0 && c.y != 1) ? 1.f : 0.f;
        cmask[j+2] = (a.z != 0 && c.z != 1) ? 1.f : 0.f;
        cmask[j+3] = (a.w != 0 && c.w != 1) ? 1.f : 0.f;
    }

    #pragma unroll
    for (int it = 0; it < 4; it++){
        const int idx = tid + it*256;
        const int r = idx >> 3, q = idx & 7;
        const uint32_t dst = (r < 64) ? (base + (uint32_t)(r*144 + q*16))
                                      : (base + 9216 + (uint32_t)((r-64)*144 + q*16));
        CP16(dst, qb + (size_t)r*QKV3 + q*8);
    }
    CP_COMMIT(); CP_WAIT0();
    __syncthreads();

    uint32_t qa[4][4];
    {
        const uint32_t qbase = (warp < 4) ? base : (base + 9216);
        const int row0 = (warp & 3) * 16;
        #pragma unroll
        for (int kc = 0; kc < 4; kc++)
            ldsm_x4(qa[kc], qbase + (uint32_t)((row0 + (lane & 15))*144
                                               + (lane >> 4)*16 + kc*32));
    }
    __syncthreads();

    auto prefetch = [&](int jt){
        const uint32_t kb = base + (uint32_t)((jt % 3) * FKV);
        const uint32_t vb = kb + 9216;
        #pragma unroll
        for (int it = 0; it < 2; it++){
            const int idx = tid + it*256;
            const int r = idx >> 3, q = idx & 7;
            const size_t gr = (size_t)(jt*64 + r) * QKV3 + q*8;
            CP16(kb + (uint32_t)(r*144 + q*16), kbase + gr);
            CP16(vb + (uint32_t)(r*144 + q*16), vbase + gr);
        }
    };
    prefetch(0); CP_COMMIT();
    prefetch(1); CP_COMMIT();

    const int qrow = i0 + warp*16;
    const bool rm0 = (mnp[b*SEQ + qrow + g    ] == 0);
    const bool rm1 = (mnp[b*SEQ + qrow + g + 8] == 0);

    float m0 = -1e30f, m1 = -1e30f, l0 = 0.f, l1 = 0.f;
    float o[8][4];
    #pragma unroll
    for (int nt = 0; nt < 8; nt++){ o[nt][0]=0.f; o[nt][1]=0.f; o[nt][2]=0.f; o[nt][3]=0.f; }

    for (int jt = 0; jt < 16; jt++){
        CP_WAIT1();
        __syncthreads();
        const uint32_t kb = base + (uint32_t)((jt % 3) * FKV);
        const uint32_t vb = kb + 9216;

        float s[8][4];
        #pragma unroll
        for (int nc = 0; nc < 8; nc++){ s[nc][0]=0.f; s[nc][1]=0.f; s[nc][2]=0.f; s[nc][3]=0.f; }
        #pragma unroll
        for (int kc = 0; kc < 4; kc++){
            #pragma unroll
            for (int np = 0; np < 4; np++){
                uint32_t kf[4];
                ldsm_x4(kf, kb + (uint32_t)((np*16 + (lane >> 4)*8 + (lane & 7))*144
                                            + ((lane >> 3) & 1)*16 + kc*32));
                MMA_F16(s[np*2    ], qa[kc], kf);
                MMA_F16(s[np*2 + 1], qa[kc], kf + 2);
            }
        }

        float mx0 = -1e30f, mx1 = -1e30f;
        #pragma unroll
        for (int nc = 0; nc < 8; nc++){
            const int j = jt*64 + nc*8 + 2*t;
            const float c0v = cmask[j], c1v = cmask[j+1];
            s[nc][0] = (rm0 || c0v == 0.f) ? -1000.f : s[nc][0]*0.125f;
            s[nc][1] = (rm0 || c1v == 0.f) ? -1000.f : s[nc][1]*0.125f;
            s[nc][2] = (rm1 || c0v == 0.f) ? -1000.f : s[nc][2]*0.125f;
            s[nc][3] = (rm1 || c1v == 0.f) ? -1000.f : s[nc][3]*0.125f;
            mx0 = fmaxf(mx0, fmaxf(s[nc][0], s[nc][1]));
            mx1 = fmaxf(mx1, fmaxf(s[nc][2], s[nc][3]));
        }
        mx0 = fmaxf(mx0, __shfl_xor_sync(0xffffffffu, mx0, 1));
        mx0 = fmaxf(mx0, __shfl_xor_sync(0xffffffffu, mx0, 2));
        mx1 = fmaxf(mx1, __shfl_xor_sync(0xffffffffu, mx1, 1));
        mx1 = fmaxf(mx1, __shfl_xor_sync(0xffffffffu, mx1, 2));

        const float nm0 = fmaxf(m0, mx0), nm1 = fmaxf(m1, mx1);
        const float a0 = __expf(m0 - nm0), a1 = __expf(m1 - nm1);

        // half2 exp2 softmax: one MUFU per value-pair, result IS the P fragment
        float r0s = 0.f, r1s = 0.f;
        uint32_t pbh[8][2];
        #pragma unroll
        for (int nc = 0; nc < 8; nc++){
            __half2 ea = h2exp2(__floats2half2_rn((s[nc][0]-nm0)*L2E, (s[nc][1]-nm0)*L2E));
            __half2 eb = h2exp2(__floats2half2_rn((s[nc][2]-nm1)*L2E, (s[nc][3]-nm1)*L2E));
            r0s += __low2float(ea) + __high2float(ea);
            r1s += __low2float(eb) + __high2float(eb);
            pbh[nc][0] = *reinterpret_cast<uint32_t*>(&ea);
            pbh[nc][1] = *reinterpret_cast<uint32_t*>(&eb);
        }
        r0s += __shfl_xor_sync(0xffffffffu, r0s, 1);
        r0s += __shfl_xor_sync(0xffffffffu, r0s, 2);
        r1s += __shfl_xor_sync(0xffffffffu, r1s, 1);
        r1s += __shfl_xor_sync(0xffffffffu, r1s, 2);

        l0 = l0*a0 + r0s; l1 = l1*a1 + r1s;
        m0 = nm0; m1 = nm1;

        #pragma unroll
        for (int nt = 0; nt < 8; nt++){
            o[nt][0] *= a0; o[nt][1] *= a0;
            o[nt][2] *= a1; o[nt][3] *= a1;
        }

        #pragma unroll
        for (int kc2 = 0; kc2 < 4; kc2++){
            uint32_t af[4] = {pbh[2*kc2][0], pbh[2*kc2][1],
                              pbh[2*kc2+1][0], pbh[2*kc2+1][1]};
            #pragma unroll
            for (int np = 0; np < 4; np++){
                uint32_t vf[4];
                ldsm_x4t(vf, vb + (uint32_t)((kc2*16 + ((lane >> 3) & 1)*8 + (lane & 7))*144
                                             + (np*2 + (lane >> 4))*16));
                MMA_F16(o[np*2    ], af, vf);
                MMA_F16(o[np*2 + 1], af, vf + 2);
            }
        }

        if (jt + 2 < 16) prefetch(jt + 2);
        CP_COMMIT();
    }

    const float inv0 = 1.0f / l0, inv1 = 1.0f / l1;
    const size_t r0 = (size_t)(b*SEQ + qrow + g);
    #pragma unroll
    for (int nt = 0; nt < 8; nt++){
        const int c = h*DHEAD + nt*8 + 2*t;
        *(uint32_t*)(att + r0      * INNER + c) = ph(o[nt][0]*inv0, o[nt][1]*inv0);
        *(uint32_t*)(att + (r0 + 8) * INNER + c) = ph(o[nt][2]*inv1, o[nt][3]*inv1);
    }
}

// ---------------------------------------------------------------------------
extern "C" void kernel_launch(void* const* d_in, const int* in_sizes, int n_in,
                              void* d_out, int out_size)
{
    const float* x    = (const float*)d_in[0];
    const float* Wqkv = (const float*)d_in[1];
    const float* Wout = (const float*)d_in[2];
    const float* bout = (const float*)d_in[3];
    const float* ln1g = (const float*)d_in[4];
    const float* ln1b = (const float*)d_in[5];
    const float* W1   = (const float*)d_in[6];
    const float* b1   = (const float*)d_in[7];
    const float* W2   = (const float*)d_in[8];
    const float* b2   = (const float*)d_in[9];
    const float* ln2g = (const float*)d_in[10];
    const float* ln2b = (const float*)d_in[11];
    const int*   mnp  = (const int*)d_in[12];
    const int*   mbt  = (const int*)d_in[13];

    float* gx = (float*)d_out;   // residual stream lives in the output buffer
    __half *gh, *gqkv, *gatt, *gmlp, *wqkv, *wout, *w1, *w2;
    cudaGetSymbolAddress((void**)&gh,   g_h);
    cudaGetSymbolAddress((void**)&gqkv, g_qkv);
    cudaGetSymbolAddress((void**)&gatt, g_att);
    cudaGetSymbolAddress((void**)&gmlp, g_mlp);
    cudaGetSymbolAddress((void**)&wqkv, g_wqkv);
    cudaGetSymbolAddress((void**)&wout, g_wout);
    cudaGetSymbolAddress((void**)&w1,   g_w1);
    cudaGetSymbolAddress((void**)&w2,   g_w2);

    cudaFuncSetAttribute(hgemm<1>, cudaFuncAttributeMaxDynamicSharedMemorySize, SMTOT);
    cudaFuncSetAttribute(hgemm<2>, cudaFuncAttributeMaxDynamicSharedMemorySize, SMTOT);
    cudaFuncSetAttribute(hgemm<3>, cudaFuncAttributeMaxDynamicSharedMemorySize, SMTOT);
    cudaFuncSetAttribute(flash_kernel, cudaFuncAttributeMaxDynamicSharedMemorySize, FLSM);

    // streaming f32 -> fp16 weight conversion (layout unchanged)
    { int n = DEPTH*DIMM*QKV3/16;  cvt16<<<(n+255)/256, 256>>>(Wqkv, wqkv, n); }
    { int n = DEPTH*INNER*DIMM/16; cvt16<<<(n+255)/256, 256>>>(Wout, wout, n); }
    { int n = DEPTH*DIMM*MLPD/16;  cvt16<<<(n+255)/256, 256>>>(W1,   w1,   n); }
    { int n = DEPTH*MLPD*DIMM/16;  cvt16<<<(n+255)/256, 256>>>(W2,   w2,   n); }

    for (int l = 0; l < DEPTH; l++) {
        const float* res = (l == 0) ? x : gx;
        ln_kernel<<<TOK/8, 256>>>(res, gh, ln1g + l*DIMM, ln1b + l*DIMM);
        hgemm<3><<<dim3(QKV3/128, TOK/128), 256, SMTOT>>>(
            gh, wqkv + (size_t)l*DIMM*QKV3, gqkv, nullptr, nullptr,
            TOK, QKV3, DIMM);
        flash_kernel<<<dim3(SEQ/128, BATCH*HEADS), 256, FLSM>>>(gqkv, gatt, mnp, mbt);
        hgemm<2><<<dim3(DIMM/128, TOK/128), 256, SMTOT>>>(
            gatt, wout + (size_t)l*INNER*DIMM, gx, bout + l*DIMM, res,
            TOK, DIMM, INNER);
        ln_kernel<<<TOK/8, 256>>>(gx, gh, ln2g + l*DIMM, ln2b + l*DIMM);
        hgemm<1><<<dim3(MLPD/128, TOK/128), 256, SMTOT>>>(
            gh, w1 + (size_t)l*DIMM*MLPD, gmlp, b1 + l*MLPD, nullptr,
            TOK, MLPD, DIMM);
        hgemm<2><<<dim3(DIMM/128, TOK/128), 256, SMTOT>>>(
            gmlp, w2 + (size_t)l*MLPD*DIMM, gx, b2 + l*DIMM, gx,
            TOK, DIMM, MLPD);
    }
    // residual stream IS d_out — no final copy needed
}

// round 15
// speedup vs baseline: 1.0096x; 1.0096x over previous
#include <cuda_runtime.h>
#include <cuda_fp16.h>
#include <math.h>
#include <stdint.h>

#define DIMM   1024
#define DEPTH  4
#define HEADS  16
#define DHEAD  64
#define MLPD   4096
#define INNER  1024
#define BATCH  4
#define SEQ    1024
#define TOK    (BATCH*SEQ)
#define QKV3   (3*INNER)

// ---------------- scratch ----------------------------------------------------
__device__ __half g_h  [TOK*DIMM];                 // LN output (fp16)
__device__ __half g_qkv[TOK*QKV3];
__device__ __half g_att[TOK*INNER];
__device__ __half g_mlp[TOK*MLPD];
// fp16 weights, ORIGINAL [K][N] layout (no transpose)
__device__ __half g_wqkv[(size_t)DEPTH*DIMM*QKV3];
__device__ __half g_wout[(size_t)DEPTH*INNER*DIMM];
__device__ __half g_w1  [(size_t)DEPTH*DIMM*MLPD];
__device__ __half g_w2  [(size_t)DEPTH*MLPD*DIMM];

__device__ __forceinline__ uint32_t smem_u32(const void* p){
    return (uint32_t)__cvta_generic_to_shared(p);
}
__device__ __forceinline__ uint32_t ph(float a, float b){
    __half2 h = __floats2half2_rn(a, b);
    return *reinterpret_cast<uint32_t*>(&h);
}
#define CP16(dst, src) asm volatile("cp.async.cg.shared.global [%0], [%1], 16;\n" :: "r"(dst), "l"(src))
#define CP_COMMIT()    asm volatile("cp.async.commit_group;\n" ::: "memory")
#define CP_WAIT1()     asm volatile("cp.async.wait_group 1;\n" ::: "memory")
#define CP_WAIT0()     asm volatile("cp.async.wait_group 0;\n" ::: "memory")

#define MMA_F16(d, a, b) \
  asm volatile("mma.sync.aligned.m16n8k16.row.col.f32.f16.f16.f32 " \
    "{%0,%1,%2,%3},{%4,%5,%6,%7},{%8,%9},{%0,%1,%2,%3};" \
    : "+f"((d)[0]),"+f"((d)[1]),"+f"((d)[2]),"+f"((d)[3]) \
    : "r"((a)[0]),"r"((a)[1]),"r"((a)[2]),"r"((a)[3]),"r"((b)[0]),"r"((b)[1]))

__device__ __forceinline__ void ldsm_x4(uint32_t* r, uint32_t a){
    asm volatile("ldmatrix.sync.aligned.m8n8.x4.shared.b16 {%0,%1,%2,%3}, [%4];"
        : "=r"(r[0]),"=r"(r[1]),"=r"(r[2]),"=r"(r[3]) : "r"(a));
}
__device__ __forceinline__ void ldsm_x4t(uint32_t* r, uint32_t a){
    asm volatile("ldmatrix.sync.aligned.m8n8.x4.trans.shared.b16 {%0,%1,%2,%3}, [%4];"
        : "=r"(r[0]),"=r"(r[1]),"=r"(r[2]),"=r"(r[3]) : "r"(a));
}

// ---------------- merged f32 -> fp16 weight convert (one launch) -------------
// Segments (blocks of 1024 float4): wqkv 3072 | wout 1024 | w1 4096 | w2 4096.
// All sizes divide exactly; no tail path.
__global__ void cvt16all(const float* __restrict__ s0, __half* __restrict__ d0,
                         const float* __restrict__ s1, __half* __restrict__ d1,
                         const float* __restrict__ s2, __half* __restrict__ d2,
                         const float* __restrict__ s3, __half* __restrict__ d3)
{
    int blk = blockIdx.x;
    const float* src; __half* dst;
    if (blk < 3072)      { src = s0; dst = d0; }
    else if (blk < 4096) { src = s1; dst = d1; blk -= 3072; }
    else if (blk < 8192) { src = s2; dst = d2; blk -= 4096; }
    else                 { src = s3; dst = d3; blk -= 8192; }
    const int base = blk * 1024 + threadIdx.x;      // float4 units
    const float4* p4 = (const float4*)src;
    uint2* o2 = (uint2*)dst;
    float4 a = __ldcs(&p4[base]),     b = __ldcs(&p4[base+256]);
    float4 c = __ldcs(&p4[base+512]), d = __ldcs(&p4[base+768]);
    uint2 oa = {ph(a.x,a.y), ph(a.z,a.w)};
    uint2 ob = {ph(b.x,b.y), ph(b.z,b.w)};
    uint2 oc = {ph(c.x,c.y), ph(c.z,c.w)};
    uint2 od = {ph(d.x,d.y), ph(d.z,d.w)};
    o2[base] = oa; o2[base+256] = ob; o2[base+512] = oc; o2[base+768] = od;
}

// ---------------- LayerNorm: warp-per-row (8 rows/block), shfl-only ----------
__global__ void ln_kernel(const float* __restrict__ in, __half* __restrict__ out,
                          const float* __restrict__ gg, const float* __restrict__ bb)
{
    const int warp = threadIdx.x >> 5, lane = threadIdx.x & 31;
    const int row = blockIdx.x * 8 + warp;
    const float4* p = (const float4*)(in + (size_t)row * DIMM);

    float4 v[8];
    float s = 0.f, s2 = 0.f;
    #pragma unroll
    for (int j = 0; j < 8; j++){
        v[j] = p[lane + j*32];
        s  += v[j].x + v[j].y + v[j].z + v[j].w;
        s2 += v[j].x*v[j].x + v[j].y*v[j].y + v[j].z*v[j].z + v[j].w*v[j].w;
    }
    #pragma unroll
    for (int o = 16; o > 0; o >>= 1){
        s  += __shfl_xor_sync(0xffffffffu, s,  o);
        s2 += __shfl_xor_sync(0xffffffffu, s2, o);
    }
    const float mean = s * (1.0f/DIMM);
    const float var  = s2 * (1.0f/DIMM) - mean*mean;
    const float rs   = rsqrtf(var + 1e-5f);

    uint2* orow = (uint2*)(out + (size_t)row * DIMM);
    #pragma unroll
    for (int j = 0; j < 8; j++){
        const float4 gv = ((const float4*)gg)[lane + j*32];
        const float4 bv = ((const float4*)bb)[lane + j*32];
        uint2 o;
        o.x = ph((v[j].x - mean)*rs*gv.x + bv.x, (v[j].y - mean)*rs*gv.y + bv.y);
        o.y = ph((v[j].z - mean)*rs*gv.z + bv.z, (v[j].w - mean)*rs*gv.w + bv.w);
        orow[lane + j*32] = o;
    }
}

// ---------------- FP16 GEMM: 128x128, B [K][N] via trans-ldsm, BK=64 ---------
// R10 schedule (measured optimum): prefetch after compute, 3 stages, 2 CTA/SM.
// EPI: 1 +bias+GELU -> fp16 ; 2 +bias+residual -> f32 ; 3 plain -> fp16
#define ABYH  18432            // 128*144
#define BBYH  17408            // 64*272
#define STGH  (ABYH+BBYH)      // 35840
#define NSTG  3
#define SMTOT (NSTG*STGH)      // 107520

template<int EPI>
__global__ void __launch_bounds__(256, 2)
hgemm(const __half* __restrict__ A, const __half* __restrict__ B,
      void* __restrict__ Cv, const float* __restrict__ bias,
      const float* __restrict__ R, int M, int Nn, int K)
{
    extern __shared__ char smc[];
    const uint32_t sb = smem_u32(smc);
    const int tid = threadIdx.x, warp = tid >> 5, lane = tid & 31;
    const int g = lane >> 2, t = lane & 3;
    const int wm = (warp >> 2) * 64;
    const int wn = (warp & 3) * 32;
    const int brow = blockIdx.y * 128;
    const int bcol = blockIdx.x * 128;

    float acc[4][4][4];
    #pragma unroll
    for (int i = 0; i < 4; i++)
      #pragma unroll
      for (int j = 0; j < 4; j++)
        { acc[i][j][0]=0.f; acc[i][j][1]=0.f; acc[i][j][2]=0.f; acc[i][j][3]=0.f; }

    auto prefetch = [&](int blk){
        const uint32_t ab = sb + (uint32_t)((blk % NSTG) * STGH);
        const uint32_t bb = ab + ABYH;
        const int kof = blk * 64;
        #pragma unroll
        for (int j = 0; j < 4; j++){
            const int c = tid + j*256;
            const int ar = c >> 3, aq = c & 7;
            CP16(ab + (uint32_t)(ar*144 + aq*16), A + (size_t)(brow+ar)*K + kof + aq*8);
            const int br2 = c >> 4, bq = c & 15;
            CP16(bb + (uint32_t)(br2*272 + bq*16), B + (size_t)(kof+br2)*Nn + bcol + bq*8);
        }
    };

    prefetch(0); CP_COMMIT();
    prefetch(1); CP_COMMIT();

    const uint32_t aoff = (uint32_t)((wm + (lane & 15))*144 + (lane >> 4)*16);
    const uint32_t boffl = (uint32_t)((lane & 15)*272 + (wn + ((lane >> 4) & 1)*8)*2) + ABYH;

    const int nk = K >> 6;
    for (int i = 0; i < nk; i++){
        CP_WAIT1();
        __syncthreads();
        const uint32_t stg = sb + (uint32_t)((i % NSTG) * STGH);
        #pragma unroll
        for (int s = 0; s < 4; s++){
            uint32_t af[4][4], bq2[2][4];
            #pragma unroll
            for (int mt = 0; mt < 4; mt++)
                ldsm_x4(af[mt], stg + aoff + (uint32_t)(mt*2304 + s*32));
            #pragma unroll
            for (int np = 0; np < 2; np++)
                ldsm_x4t(bq2[np], stg + boffl + (uint32_t)(s*4352 + np*32));
            #pragma unroll
            for (int mt = 0; mt < 4; mt++)
              #pragma unroll
              for (int nt = 0; nt < 4; nt++)
                MMA_F16(acc[mt][nt], af[mt], &bq2[nt >> 1][(nt & 1)*2]);
        }
        if (i + 2 < nk) prefetch(i + 2);
        CP_COMMIT();
    }

    #pragma unroll
    for (int mt = 0; mt < 4; mt++){
        const int r0 = brow + wm + mt*16 + g;
        #pragma unroll
        for (int nt = 0; nt < 4; nt++){
            const int c = bcol + wn + nt*8 + 2*t;
            float v[4] = {acc[mt][nt][0], acc[mt][nt][1], acc[mt][nt][2], acc[mt][nt][3]};
            if (EPI == 1 || EPI == 2){
                const float b0 = bias[c], b1 = bias[c+1];
                v[0]+=b0; v[1]+=b1; v[2]+=b0; v[3]+=b1;
            }
            if (EPI == 1){
                #pragma unroll
                for (int q = 0; q < 4; q++)
                    v[q] = 0.5f * v[q] * (1.0f + erff(v[q] * 0.70710678118654752f));
            }
            if (EPI == 2){
                float* Cf = (float*)Cv;
                const float2 r0v = *(const float2*)(R + (size_t)r0*Nn + c);
                const float2 r1v = *(const float2*)(R + (size_t)(r0+8)*Nn + c);
                float2 o0 = {v[0]+r0v.x, v[1]+r0v.y}, o1 = {v[2]+r1v.x, v[3]+r1v.y};
                *(float2*)(Cf + (size_t)r0    *Nn + c) = o0;
                *(float2*)(Cf + (size_t)(r0+8)*Nn + c) = o1;
            } else {
                __half* Ch = (__half*)Cv;
                *(uint32_t*)(Ch + (size_t)r0    *Nn + c) = ph(v[0], v[1]);
                *(uint32_t*)(Ch + (size_t)(r0+8)*Nn + c) = ph(v[2], v[3]);
            }
        }
    }
}

// ---------------- Fused fp16 flash attention, 3-stage K/V (R10 schedule) -----
#define FKV   18432
#define FLSM  (3*FKV + 4096)

__global__ void __launch_bounds__(256, 2)
flash_kernel(const __half* __restrict__ qkv, __half* __restrict__ att,
             const int* __restrict__ mnp, const int* __restrict__ mbt)
{
    extern __shared__ char fsm[];
    const uint32_t base = smem_u32(fsm);
    float* cmask = (float*)(fsm + 3*FKV);

    const int tid = threadIdx.x, warp = tid >> 5, lane = tid & 31;
    const int g = lane >> 2, t = lane & 3;
    const int bh = blockIdx.y, b = bh >> 4, h = bh & 15;
    const int i0 = blockIdx.x * 128;

    const __half* qb    = qkv + (size_t)(b*SEQ + i0) * QKV3 + h*DHEAD;
    const __half* kbase = qkv + (size_t)(b*SEQ) * QKV3 + INNER   + h*DHEAD;
    const __half* vbase = qkv + (size_t)(b*SEQ) * QKV3 + 2*INNER + h*DHEAD;

    {
        const int j = tid * 4;
        const int4 a = *(const int4*)(mnp + b*SEQ + j);
        const int4 c = *(const int4*)(mbt + b*SEQ + j);
        cmask[j+0] = (a.x != 0 && c.x != 1) ? 1.f : 0.f;
        cmask[j+1] = (a.y != 0 && c.y != 1) ? 1.f : 0.f;
        cmask[j+2] = (a.z != 0 && c.z != 1) ? 1.f : 0.f;
        cmask[j+3] = (a.w != 0 && c.w != 1) ? 1.f : 0.f;
    }

    #pragma unroll
    for (int it = 0; it < 4; it++){
        const int idx = tid + it*256;
        const int r = idx >> 3, q = idx & 7;
        const uint32_t dst = (r < 64) ? (base + (uint32_t)(r*144 + q*16))
                                      : (base + 9216 + (uint32_t)((r-64)*144 + q*16));
        CP16(dst, qb + (size_t)r*QKV3 + q*8);
    }
    CP_COMMIT(); CP_WAIT0();
    __syncthreads();

    uint32_t qa[4][4];
    {
        const uint32_t qbase = (warp < 4) ? base : (base + 9216);
        const int row0 = (warp & 3) * 16;
        #pragma unroll
        for (int kc = 0; kc < 4; kc++)
            ldsm_x4(qa[kc], qbase + (uint32_t)((row0 + (lane & 15))*144
                                               + (lane >> 4)*16 + kc*32));
    }
    __syncthreads();

    auto prefetch = [&](int jt){
        const uint32_t kb = base + (uint32_t)((jt % 3) * FKV);
        const uint32_t vb = kb + 9216;
        #pragma unroll
        for (int it = 0; it < 2; it++){
            const int idx = tid + it*256;
            const int r = idx >> 3, q = idx & 7;
            const size_t gr = (size_t)(jt*64 + r) * QKV3 + q*8;
            CP16(kb + (uint32_t)(r*144 + q*16), kbase + gr);
            CP16(vb + (uint32_t)(r*144 + q*16), vbase + gr);
        }
    };
    prefetch(0); CP_COMMIT();
    prefetch(1); CP_COMMIT();

    const int qrow = i0 + warp*16;
    const bool rm0 = (mnp[b*SEQ + qrow + g    ] == 0);
    const bool rm1 = (mnp[b*SEQ + qrow + g + 8] == 0);

    float m0 = -1e30f, m1 = -1e30f, l0 = 0.f, l1 = 0.f;
    float o[8][4];
    #pragma unroll
    for (int nt = 0; nt < 8; nt++){ o[nt][0]=0.f; o[nt][1]=0.f; o[nt][2]=0.f; o[nt][3]=0.f; }

    for (int jt = 0; jt < 16; jt++){
        CP_WAIT1();
        __syncthreads();
        const uint32_t kb = base + (uint32_t)((jt % 3) * FKV);
        const uint32_t vb = kb + 9216;

        float s[8][4];
        #pragma unroll
        for (int nc = 0; nc < 8; nc++){ s[nc][0]=0.f; s[nc][1]=0.f; s[nc][2]=0.f; s[nc][3]=0.f; }
        #pragma unroll
        for (int kc = 0; kc < 4; kc++){
            #pragma unroll
            for (int np = 0; np < 4; np++){
                uint32_t kf[4];
                ldsm_x4(kf, kb + (uint32_t)((np*16 + (lane >> 4)*8 + (lane & 7))*144
                                            + ((lane >> 3) & 1)*16 + kc*32));
                MMA_F16(s[np*2    ], qa[kc], kf);
                MMA_F16(s[np*2 + 1], qa[kc], kf + 2);
            }
        }

        float mx0 = -1e30f, mx1 = -1e30f;
        #pragma unroll
        for (int nc = 0; nc < 8; nc++){
            const int j = jt*64 + nc*8 + 2*t;
            const float c0v = cmask[j], c1v = cmask[j+1];
            s[nc][0] = (rm0 || c0v == 0.f) ? -1000.f : s[nc][0]*0.125f;
            s[nc][1] = (rm0 || c1v == 0.f) ? -1000.f : s[nc][1]*0.125f;
            s[nc][2] = (rm1 || c0v == 0.f) ? -1000.f : s[nc][2]*0.125f;
            s[nc][3] = (rm1 || c1v == 0.f) ? -1000.f : s[nc][3]*0.125f;
            mx0 = fmaxf(mx0, fmaxf(s[nc][0], s[nc][1]));
            mx1 = fmaxf(mx1, fmaxf(s[nc][2], s[nc][3]));
        }
        mx0 = fmaxf(mx0, __shfl_xor_sync(0xffffffffu, mx0, 1));
        mx0 = fmaxf(mx0, __shfl_xor_sync(0xffffffffu, mx0, 2));
        mx1 = fmaxf(mx1, __shfl_xor_sync(0xffffffffu, mx1, 1));
        mx1 = fmaxf(mx1, __shfl_xor_sync(0xffffffffu, mx1, 2));

        const float nm0 = fmaxf(m0, mx0), nm1 = fmaxf(m1, mx1);
        const float a0 = __expf(m0 - nm0), a1 = __expf(m1 - nm1);

        float r0s = 0.f, r1s = 0.f;
        uint32_t pbh[8][2];
        #pragma unroll
        for (int nc = 0; nc < 8; nc++){
            const float e0 = __expf(s[nc][0] - nm0);
            const float e1 = __expf(s[nc][1] - nm0);
            const float e2 = __expf(s[nc][2] - nm1);
            const float e3 = __expf(s[nc][3] - nm1);
            r0s += e0 + e1; r1s += e2 + e3;
            pbh[nc][0] = ph(e0, e1);
            pbh[nc][1] = ph(e2, e3);
        }
        r0s += __shfl_xor_sync(0xffffffffu, r0s, 1);
        r0s += __shfl_xor_sync(0xffffffffu, r0s, 2);
        r1s += __shfl_xor_sync(0xffffffffu, r1s, 1);
        r1s += __shfl_xor_sync(0xffffffffu, r1s, 2);

        l0 = l0*a0 + r0s; l1 = l1*a1 + r1s;
        m0 = nm0; m1 = nm1;

        #pragma unroll
        for (int nt = 0; nt < 8; nt++){
            o[nt][0] *= a0; o[nt][1] *= a0;
            o[nt][2] *= a1; o[nt][3] *= a1;
        }

        #pragma unroll
        for (int kc2 = 0; kc2 < 4; kc2++){
            uint32_t af[4] = {pbh[2*kc2][0], pbh[2*kc2][1],
                              pbh[2*kc2+1][0], pbh[2*kc2+1][1]};
            #pragma unroll
            for (int np = 0; np < 4; np++){
                uint32_t vf[4];
                ldsm_x4t(vf, vb + (uint32_t)((kc2*16 + ((lane >> 3) & 1)*8 + (lane & 7))*144
                                             + (np*2 + (lane >> 4))*16));
                MMA_F16(o[np*2    ], af, vf);
                MMA_F16(o[np*2 + 1], af, vf + 2);
            }
        }

        if (jt + 2 < 16) prefetch(jt + 2);
        CP_COMMIT();
    }

    const float inv0 = 1.0f / l0, inv1 = 1.0f / l1;
    const size_t r0 = (size_t)(b*SEQ + qrow + g);
    #pragma unroll
    for (int nt = 0; nt < 8; nt++){
        const int c = h*DHEAD + nt*8 + 2*t;
        *(uint32_t*)(att + r0      * INNER + c) = ph(o[nt][0]*inv0, o[nt][1]*inv0);
        *(uint32_t*)(att + (r0 + 8) * INNER + c) = ph(o[nt][2]*inv1, o[nt][3]*inv1);
    }
}

// ---------------------------------------------------------------------------
extern "C" void kernel_launch(void* const* d_in, const int* in_sizes, int n_in,
                              void* d_out, int out_size)
{
    const float* x    = (const float*)d_in[0];
    const float* Wqkv = (const float*)d_in[1];
    const float* Wout = (const float*)d_in[2];
    const float* bout = (const float*)d_in[3];
    const float* ln1g = (const float*)d_in[4];
    const float* ln1b = (const float*)d_in[5];
    const float* W1   = (const float*)d_in[6];
    const float* b1   = (const float*)d_in[7];
    const float* W2   = (const float*)d_in[8];
    const float* b2   = (const float*)d_in[9];
    const float* ln2g = (const float*)d_in[10];
    const float* ln2b = (const float*)d_in[11];
    const int*   mnp  = (const int*)d_in[12];
    const int*   mbt  = (const int*)d_in[13];

    float* gx = (float*)d_out;   // residual stream lives in the output buffer
    __half *gh, *gqkv, *gatt, *gmlp, *wqkv, *wout, *w1, *w2;
    cudaGetSymbolAddress((void**)&gh,   g_h);
    cudaGetSymbolAddress((void**)&gqkv, g_qkv);
    cudaGetSymbolAddress((void**)&gatt, g_att);
    cudaGetSymbolAddress((void**)&gmlp, g_mlp);
    cudaGetSymbolAddress((void**)&wqkv, g_wqkv);
    cudaGetSymbolAddress((void**)&wout, g_wout);
    cudaGetSymbolAddress((void**)&w1,   g_w1);
    cudaGetSymbolAddress((void**)&w2,   g_w2);

    cudaFuncSetAttribute(hgemm<1>, cudaFuncAttributeMaxDynamicSharedMemorySize, SMTOT);
    cudaFuncSetAttribute(hgemm<2>, cudaFuncAttributeMaxDynamicSharedMemorySize, SMTOT);
    cudaFuncSetAttribute(hgemm<3>, cudaFuncAttributeMaxDynamicSharedMemorySize, SMTOT);
    cudaFuncSetAttribute(flash_kernel, cudaFuncAttributeMaxDynamicSharedMemorySize, FLSM);

    // single merged f32 -> fp16 weight conversion
    cvt16all<<<12288, 256>>>(Wqkv, wqkv, Wout, wout, W1, w1, W2, w2);

    for (int l = 0; l < DEPTH; l++) {
        // layer 0 reads the residual directly from the input buffer; the
        // layer-0 out-proj writes every element of gx before anything reads it.
        const float* res = (l == 0) ? x : gx;
        ln_kernel<<<TOK/8, 256>>>(res, gh, ln1g + l*DIMM, ln1b + l*DIMM);
        hgemm<3><<<dim3(QKV3/128, TOK/128), 256, SMTOT>>>(
            gh, wqkv + (size_t)l*DIMM*QKV3, gqkv, nullptr, nullptr,
            TOK, QKV3, DIMM);
        flash_kernel<<<dim3(SEQ/128, BATCH*HEADS), 256, FLSM>>>(gqkv, gatt, mnp, mbt);
        hgemm<2><<<dim3(DIMM/128, TOK/128), 256, SMTOT>>>(
            gatt, wout + (size_t)l*INNER*DIMM, gx, bout + l*DIMM, res,
            TOK, DIMM, INNER);
        ln_kernel<<<TOK/8, 256>>>(gx, gh, ln2g + l*DIMM, ln2b + l*DIMM);
        hgemm<1><<<dim3(MLPD/128, TOK/128), 256, SMTOT>>>(
            gh, w1 + (size_t)l*DIMM*MLPD, gmlp, b1 + l*MLPD, nullptr,
            TOK, MLPD, DIMM);
        hgemm<2><<<dim3(DIMM/128, TOK/128), 256, SMTOT>>>(
            gmlp, w2 + (size_t)l*MLPD*DIMM, gx, b2 + l*DIMM, gx,
            TOK, DIMM, MLPD);
    }
    // residual stream IS d_out — no final copy needed
}